// round 11
// baseline (speedup 1.0000x reference)
#include <cuda_runtime.h>
#include <cuda_fp16.h>
#include <mma.h>
using namespace nvcuda;

#define NB 4
#define NC 64
#define NN 8192
#define NK 16
#define NO 64
#define EPSV 1e-5f

// Combined y, fp16: [b][n][128] halves. ch 0-63  = y1 = inv*(W1-W2)@x  (gather via e1)
//                                      ch 64-127 = y2 = inv*W2@x + shift (gather via e0)
__device__ __align__(16) __half g_y[(size_t)NB * NN * 128];

#define XH_LD 72    // sXh [c][n] fp16 rows (64 + 8 pad)
#define WH_LD 136   // sWh [c][o] fp16 rows (128 + 8 pad)
#define ST_LD 40    // epilogue staging row stride in floats

#define SMEM_XH    0                      // 64*72*2  = 9216
#define SMEM_WH    9216                   // 64*136*2 = 17408
#define SMEM_SHIFT 26624                  // 128 floats = 512
#define SMEM_TOT   27136
// Epilogue staging reuses bytes [0, 20480) (8 warps x 16 x 40 floats).

// ---------------------------------------------------------------------------
// Kernel A (tensor cores): 64-node x 128-out block, grid 512 (~3.5 blk/SM).
// 8 warps = 4 node-groups x 2 out-halves; warp = 16 nodes x 64 outs
// (4 wmma tiles), 4 k-steps. A = X tile col_major (gmem layout [c][n]).
// B = folded W fp16. BN shift added in epilogue.
// ---------------------------------------------------------------------------
__global__ __launch_bounds__(256) void kA(
    const float* __restrict__ x, const float* __restrict__ W,
    const float* __restrict__ gamma, const float* __restrict__ beta,
    const float* __restrict__ rmean, const float* __restrict__ rvar)
{
    __shared__ __align__(16) char smem[SMEM_TOT];
    __half* sXh    = (__half*)(smem + SMEM_XH);
    __half* sWh    = (__half*)(smem + SMEM_WH);
    float*  sshift = (float*)(smem + SMEM_SHIFT);
    __shared__ float sinv[64];

    const int tid = threadIdx.x;
    const int b   = blockIdx.y;
    const int n0b = blockIdx.x * 64;
    const int w   = tid >> 5;
    const int lane = tid & 31;

    // BN constants.
    if (tid < 64) sinv[tid] = gamma[tid] * rsqrtf(rvar[tid] + EPSV);
    if (tid < 128) {
        float s = 0.f;
        if (tid >= 64) {
            int o2 = tid - 64;
            s = beta[o2] - rmean[o2] * gamma[o2] * rsqrtf(rvar[o2] + EPSV);
        }
        sshift[tid] = s;
    }

    // Stage X tile: [64 c][64 n] fp32 -> fp16, coalesced float4 reads.
    {
        const float4* xp = (const float4*)(x + (size_t)b * NC * NN + n0b);
        for (int i = tid; i < 64 * 16; i += 256) {
            int c = i >> 4, j = i & 15;
            float4 v = xp[(size_t)c * (NN / 4) + j];
            __half2* dst = (__half2*)&sXh[c * XH_LD + 4 * j];
            dst[0] = __floats2half2_rn(v.x, v.y);
            dst[1] = __floats2half2_rn(v.z, v.w);
        }
    }
    __syncthreads();   // sinv ready for W fold

    // Stage folded W: sWh[c][o]; o<64 -> (W1-W2)*inv, o>=64 -> W2*inv.
    for (int i = tid; i < 2048; i += 256) {
        int q = i >> 6, c = i & 63;
        int o0 = q * 4;
        float v[4];
        if (o0 < 64) {
#pragma unroll
            for (int j = 0; j < 4; j++) {
                int o = o0 + j;
                v[j] = (W[o * 128 + c] - W[o * 128 + 64 + c]) * sinv[o];
            }
        } else {
#pragma unroll
            for (int j = 0; j < 4; j++) {
                int o2 = o0 + j - 64;
                v[j] = W[o2 * 128 + 64 + c] * sinv[o2];
            }
        }
        __half2* dst = (__half2*)&sWh[c * WH_LD + o0];
        dst[0] = __floats2half2_rn(v[0], v[1]);
        dst[1] = __floats2half2_rn(v[2], v[3]);
    }
    __syncthreads();

    // Mainloop: warp = nodes [ng*16,+16) x outs [oh*64,+64).
    const int ng = w & 3, oh = w >> 2;
    const int n0 = ng * 16, o0 = oh * 64;
    wmma::fragment<wmma::matrix_a, 16, 16, 16, __half, wmma::col_major> af;
    wmma::fragment<wmma::matrix_b, 16, 16, 16, __half, wmma::row_major> bf;
    wmma::fragment<wmma::accumulator, 16, 16, 16, float> acc[4];
#pragma unroll
    for (int t = 0; t < 4; t++) wmma::fill_fragment(acc[t], 0.0f);

#pragma unroll
    for (int k = 0; k < 4; k++) {
        wmma::load_matrix_sync(af, sXh + k * 16 * XH_LD + n0, XH_LD);
#pragma unroll
        for (int t = 0; t < 4; t++) {
            wmma::load_matrix_sync(bf, sWh + k * 16 * WH_LD + o0 + t * 16, WH_LD);
            wmma::mma_sync(acc[t], af, bf, acc[t]);
        }
    }
    __syncthreads();   // smem about to be reused for staging

    // Epilogue: 2 passes of 32 outs via per-warp smem staging.
    float* st = (float*)smem + w * 16 * ST_LD;
    const int r = lane & 15, h = lane >> 4;
#pragma unroll
    for (int p = 0; p < 2; p++) {
        wmma::store_matrix_sync(st,      acc[2 * p],     ST_LD, wmma::mem_row_major);
        wmma::store_matrix_sync(st + 16, acc[2 * p + 1], ST_LD, wmma::mem_row_major);
        __syncwarp();
        int ob = o0 + p * 32 + h * 16;
        const float* row = st + r * ST_LD + h * 16;
        __half2 hh[8];
#pragma unroll
        for (int j = 0; j < 4; j++) {
            float4 f = *(const float4*)(row + 4 * j);
            float4 s = *(const float4*)(sshift + ob + 4 * j);
            hh[2 * j]     = __floats2half2_rn(f.x + s.x, f.y + s.y);
            hh[2 * j + 1] = __floats2half2_rn(f.z + s.z, f.w + s.w);
        }
        int n = n0b + n0 + r;
        *(uint4*)(&g_y[(((size_t)b * NN + n) << 7) + ob])     = *(uint4*)&hh[0];
        *(uint4*)(&g_y[(((size_t)b * NN + n) << 7) + ob + 8]) = *(uint4*)&hh[4];
        __syncwarp();
    }
}

// ---------------------------------------------------------------------------
// Kernel B: edge gather + leaky + max, fp16 y, wide gathers, 2 nodes/thread.
// Block = 64 nodes, 256 threads. Warp handles 8 nodes: 4 via lane>>3 plus a
// +4 partner -> 4 independent LDG.128 per k per thread (2x MLP vs R9).
// ---------------------------------------------------------------------------
__global__ __launch_bounds__(256) void kB(
    const int* __restrict__ ei, float* __restrict__ out)
{
    __shared__ int  sIdx[2048];      // [0:1024) e0 rows, [1024:2048) e1 rows
    __shared__ float sm[64 * 66];

    const int tid  = threadIdx.x;
    const int w    = tid >> 5;
    const int lane = tid & 31;
    const int b    = blockIdx.y;
    const int n0   = blockIdx.x * 64;

    const int* e0 = ei + (size_t)b * NN * NK + (size_t)n0 * NK;   // 1024 ints
    const int* e1 = e0 + (size_t)NB * NN * NK;

    // Stage indices: 512 int4 loads, 2 per thread.
    ((int4*)sIdx)[tid]       = ((const int4*)e0)[tid];
    ((int4*)sIdx)[256 + tid] = ((const int4*)e1)[tid];
    __syncthreads();

    const char* yb = (const char*)g_y + ((size_t)b * NN * 256);
    const __half2 NEGI  = __half2half2(__ushort_as_half(0xFC00));
    const __half2 SLOPE = __float2half2_rn(0.2f);

    const int nlA = w * 8 + (lane >> 3);   // first node (0..63)
    const int nlB = nlA + 4;               // second node
    const int sub = lane & 7;              // 8-ch slice
    const int* iA0 = &sIdx[nlA * NK];
    const int* iA1 = &sIdx[1024 + nlA * NK];
    const int* iB0 = &sIdx[nlB * NK];
    const int* iB1 = &sIdx[1024 + nlB * NK];

    __half2 mA[4] = {NEGI, NEGI, NEGI, NEGI};
    __half2 mB[4] = {NEGI, NEGI, NEGI, NEGI};
#pragma unroll
    for (int k = 0; k < 16; k++) {
        uint4 avA = *(const uint4*)(yb + (iA1[k] << 8) + (sub << 4));
        uint4 cvA = *(const uint4*)(yb + (iA0[k] << 8) + 128 + (sub << 4));
        uint4 avB = *(const uint4*)(yb + (iB1[k] << 8) + (sub << 4));
        uint4 cvB = *(const uint4*)(yb + (iB0[k] << 8) + 128 + (sub << 4));
        const __half2* aA = (const __half2*)&avA;
        const __half2* cA = (const __half2*)&cvA;
        const __half2* aB = (const __half2*)&avB;
        const __half2* cB = (const __half2*)&cvB;
#pragma unroll
        for (int q = 0; q < 4; q++) {
            __half2 hA = __hadd2(aA[q], cA[q]);
            hA = __hmax2(hA, __hmul2(hA, SLOPE));
            mA[q] = __hmax2(mA[q], hA);
            __half2 hB = __hadd2(aB[q], cB[q]);
            hB = __hmax2(hB, __hmul2(hB, SLOPE));
            mB[q] = __hmax2(mB[q], hB);
        }
    }
#pragma unroll
    for (int q = 0; q < 4; q++) {
        float2 fA = __half22float2(mA[q]);
        float2 fB = __half22float2(mB[q]);
        sm[(sub * 8 + 2 * q)     * 66 + nlA] = fA.x;
        sm[(sub * 8 + 2 * q + 1) * 66 + nlA] = fA.y;
        sm[(sub * 8 + 2 * q)     * 66 + nlB] = fB.x;
        sm[(sub * 8 + 2 * q + 1) * 66 + nlB] = fB.y;
    }
    __syncthreads();

#pragma unroll
    for (int i = 0; i < 8; i++) {
        int o = i * 8 + w;
        float* dst = out + ((size_t)(b * NO + o)) * NN + n0;
        dst[lane]      = sm[o * 66 + lane];
        dst[lane + 32] = sm[o * 66 + 32 + lane];
    }
}

extern "C" void kernel_launch(void* const* d_in, const int* in_sizes, int n_in,
                              void* d_out, int out_size)
{
    const float* x     = (const float*)d_in[0];
    const int*   ei    = (const int*)d_in[1];
    const float* W     = (const float*)d_in[2];
    const float* gamma = (const float*)d_in[3];
    const float* beta  = (const float*)d_in[4];
    const float* rmean = (const float*)d_in[5];
    const float* rvar  = (const float*)d_in[6];
    float*       out   = (float*)d_out;

    kA<<<dim3(NN / 64, NB), 256>>>(x, W, gamma, beta, rmean, rvar);
    kB<<<dim3(NN / 64, NB), 256>>>(ei, out);
}